// round 6
// baseline (speedup 1.0000x reference)
#include <cuda_runtime.h>
#include <cuda_bf16.h>
#include <cstdint>

// Problem constants
#define B_DIM 128
#define L_DIM 1024
#define D_DIM 128
#define DVF   32          // D/4 float4 groups (full row)
#define DT    8           // float4 groups per D-tile (D split 4 ways)
#define NDT   4
#define TSTART 128        // output start positions per L tile
#define NPOS  159         // input positions needed: TSTART + 31
#define NS4   156         // sliding-4-sum rows needed: TSTART + 28
#define NTHREADS 512

// Output row offsets for window sizes 4, 8, 16, 32
#define OFF4  0
#define OFF8  1021
#define OFF16 2038
#define OFF32 3047
#define ROWS  4040

// Shared memory layout (bytes):
//   xst  : 160*DT float4  raw x staging (cp.async target)   = 20480
//   s4   : 156*DT float4  sliding 4-sums                    = 19968
//   inv  : 4*TSTART float                                   = 2048
//   fmsk : 160 float                                        = 640
//   msk  : 160 int                                          = 640
#define XST_F4   (160 * DT)
#define S4_F4    (NS4 * DT)
#define SMEM_BYTES (XST_F4 * 16 + S4_F4 * 16 + 4 * TSTART * 4 + 160 * 4 + 160 * 4)

__device__ __forceinline__ float4 add4(float4 a, float4 b) {
    return make_float4(a.x + b.x, a.y + b.y, a.z + b.z, a.w + b.w);
}
__device__ __forceinline__ float4 scl4(float4 a, float s) {
    return make_float4(a.x * s, a.y * s, a.z * s, a.w * s);
}
__device__ __forceinline__ float4 fma4(float m, float4 x, float4 acc) {
    return make_float4(fmaf(m, x.x, acc.x), fmaf(m, x.y, acc.y),
                       fmaf(m, x.z, acc.z), fmaf(m, x.w, acc.w));
}

__device__ __forceinline__ uint32_t smem_u32(const void* p) {
    return (uint32_t)__cvta_generic_to_shared(p);
}

extern __shared__ float smem_raw[];

__global__ __launch_bounds__(NTHREADS, 4)
void msse_kernel(const float* __restrict__ x,
                 const int* __restrict__ mask,
                 float* __restrict__ out)
{
    const int s0    = blockIdx.x * TSTART;    // global start of this L tile
    const int dbase = blockIdx.y * DT;        // float4-group base of D tile
    const int b     = blockIdx.z;
    const int tid   = threadIdx.x;

    float4* xst  = reinterpret_cast<float4*>(smem_raw);          // 160*DT f4
    float4* s4   = xst + XST_F4;                                 // 156*DT f4
    float*  inv  = reinterpret_cast<float*>(s4 + S4_F4);         // 4*TSTART
    float*  fmsk = inv + 4 * TSTART;                             // 160
    int*    msk  = reinterpret_cast<int*>(fmsk + 160);           // 160

    const float4* xrow = reinterpret_cast<const float4*>(x + (size_t)b * L_DIM * D_DIM);

    // ---- phase A: fire ALL x-tile reads via cp.async immediately (no deps).
    //      Rows past L zero-filled via src_size=0. 159 rows x DT groups. ----
    {
        const uint32_t xst_base = smem_u32(xst);
        for (int i = tid; i < NPOS * DT; i += NTHREADS) {
            int p = i >> 3;
            int q = i & 7;
            int g = s0 + p;
            int gc = g < L_DIM ? g : (L_DIM - 1);       // clamped valid address
            const float4* src = xrow + (size_t)gc * DVF + dbase + q;
            uint32_t dst = xst_base + (uint32_t)i * 16u;
            int sz = (g < L_DIM) ? 16 : 0;              // 0 -> zero-fill
            asm volatile("cp.async.cg.shared.global [%0], [%1], 16, %2;\n"
                         :: "r"(dst), "l"(src), "r"(sz));
        }
        asm volatile("cp.async.commit_group;\n" ::: "memory");
    }

    // ---- phase B: mask load (tiny, regular LDG) ----
    if (tid < 160) {
        int g = s0 + tid;
        int m = (tid < NPOS && g < L_DIM) ? mask[(size_t)b * L_DIM + g] : 0;
        msk[tid]  = m;
        fmsk[tid] = (float)m;
    }

    asm volatile("cp.async.wait_group 0;\n" ::: "memory");
    __syncthreads();

    // ---- phase C: build s4 from staging (LDS + FFMA, latency-tolerant),
    //      plus per-start reciprocals on threads 0..127. ----
    for (int i = tid; i < NS4 * DT; i += NTHREADS) {
        int p = i >> 3;
        int q = i & 7;
        const float4* xp = xst + p * DT + q;
        float4 acc = make_float4(0.f, 0.f, 0.f, 0.f);
        #pragma unroll
        for (int k = 0; k < 4; k++)
            acc = fma4(fmsk[p + k], xp[k * DT], acc);
        s4[i] = acc;
    }

    if (tid < TSTART) {
        int j = tid;
        int c = 0;
        #pragma unroll
        for (int k = 0; k < 4; k++)  c += msk[j + k];
        int c4 = c;
        #pragma unroll
        for (int k = 4; k < 8; k++)  c += msk[j + k];
        int c8 = c;
        #pragma unroll
        for (int k = 8; k < 16; k++) c += msk[j + k];
        int c16 = c;
        #pragma unroll
        for (int k = 16; k < 32; k++) c += msk[j + k];
        int c32 = c;
        inv[0 * TSTART + j] = 1.0f / (float)(c4  > 1 ? c4  : 1);
        inv[1 * TSTART + j] = 1.0f / (float)(c8  > 1 ? c8  : 1);
        inv[2 * TSTART + j] = 1.0f / (float)(c16 > 1 ? c16 : 1);
        inv[3 * TSTART + j] = 1.0f / (float)(c32 > 1 ? c32 : 1);
    }
    __syncthreads();

    // ---- phase D: pair-start sweep. Each thread produces ALL windows for
    //      starts j0 and j1=j0+4 from one pass over a0..a8 (9 LDS / 2 starts). ----
    {
        const int q   = tid & 7;
        const int idx = tid >> 3;        // 0..63
        const int jm  = idx & 3;
        const int k   = idx >> 2;        // 0..15
        const int j0  = jm + 8 * k;      // first start of pair
        const int j1  = j0 + 4;
        const int gi0 = s0 + j0;
        const int gi1 = s0 + j1;
        const int oq  = dbase + q;

        float4* outb = reinterpret_cast<float4*>(out + (size_t)b * ROWS * D_DIM);
        const float4* sp = s4 + j0 * DT + q;   // a_k = sp[k*4*DT]

        // a0
        float4 a    = sp[0];
        float4 accA = a;                                   // j0 running sum
        if (gi0 <= L_DIM - 4)
            outb[(OFF4 + gi0) * DVF + oq] = scl4(a, inv[0 * TSTART + j0]);
        // a1
        a = sp[4 * DT];
        float4 accB = a;                                   // j1 running sum
        if (gi1 <= L_DIM - 4)
            outb[(OFF4 + gi1) * DVF + oq] = scl4(a, inv[0 * TSTART + j1]);
        accA = add4(accA, a);
        if (gi0 <= L_DIM - 8)
            outb[(OFF8 + gi0) * DVF + oq] = scl4(accA, inv[1 * TSTART + j0]);
        // a2
        a = sp[8 * DT];
        accB = add4(accB, a);
        if (gi1 <= L_DIM - 8)
            outb[(OFF8 + gi1) * DVF + oq] = scl4(accB, inv[1 * TSTART + j1]);
        accA = add4(accA, a);
        // a3
        a = sp[12 * DT];
        accA = add4(accA, a);
        if (gi0 <= L_DIM - 16)
            outb[(OFF16 + gi0) * DVF + oq] = scl4(accA, inv[2 * TSTART + j0]);
        accB = add4(accB, a);
        // a4
        a = sp[16 * DT];
        accB = add4(accB, a);
        if (gi1 <= L_DIM - 16)
            outb[(OFF16 + gi1) * DVF + oq] = scl4(accB, inv[2 * TSTART + j1]);
        accA = add4(accA, a);
        // a5
        a = sp[20 * DT];
        accA = add4(accA, a);
        accB = add4(accB, a);
        // a6
        a = sp[24 * DT];
        accA = add4(accA, a);
        accB = add4(accB, a);
        // a7
        a = sp[28 * DT];
        accA = add4(accA, a);
        if (gi0 <= L_DIM - 32)
            outb[(OFF32 + gi0) * DVF + oq] = scl4(accA, inv[3 * TSTART + j0]);
        accB = add4(accB, a);
        // a8
        a = sp[32 * DT];
        accB = add4(accB, a);
        if (gi1 <= L_DIM - 32)
            outb[(OFF32 + gi1) * DVF + oq] = scl4(accB, inv[3 * TSTART + j1]);
    }
}

extern "C" void kernel_launch(void* const* d_in, const int* in_sizes, int n_in,
                              void* d_out, int out_size)
{
    const float* x    = (const float*)d_in[0];
    const int*   mask = (const int*)d_in[1];
    float*       out  = (float*)d_out;

    cudaFuncSetAttribute(msse_kernel,
                         cudaFuncAttributeMaxDynamicSharedMemorySize, SMEM_BYTES);

    dim3 grid(L_DIM / TSTART, NDT, B_DIM);   // 8 x 4 x 128 = 4096 CTAs
    msse_kernel<<<grid, NTHREADS, SMEM_BYTES>>>(x, mask, out);
}

// round 7
// speedup vs baseline: 1.2963x; 1.2963x over previous
#include <cuda_runtime.h>
#include <cuda_bf16.h>

// Problem constants
#define B_DIM 128
#define L_DIM 1024
#define D_DIM 128
#define DVF   32          // D/4 float4 groups (full row)
#define DT    8           // float4 groups per D-tile (D split 4 ways)
#define NDT   4
#define TSTART 128        // output start positions per L tile
#define NS4   156         // sliding-4-sum rows needed: TSTART + 28
#define NTHREADS 512

// Output row offsets for window sizes 4, 8, 16, 32
#define OFF4  0
#define OFF8  1021
#define OFF16 2038
#define OFF32 3047
#define ROWS  4040

// Shared memory (floats): s4 (NS4*DT float4) + inv (4*TSTART)
#define SMEM_FLOATS (NS4 * DT * 4 + 4 * TSTART)
#define SMEM_BYTES  (SMEM_FLOATS * 4)

__device__ __forceinline__ float4 add4(float4 a, float4 b) {
    return make_float4(a.x + b.x, a.y + b.y, a.z + b.z, a.w + b.w);
}
__device__ __forceinline__ float4 scl4(float4 a, float s) {
    return make_float4(a.x * s, a.y * s, a.z * s, a.w * s);
}
__device__ __forceinline__ float4 fma4(float m, float4 x, float4 acc) {
    return make_float4(fmaf(m, x.x, acc.x), fmaf(m, x.y, acc.y),
                       fmaf(m, x.z, acc.z), fmaf(m, x.w, acc.w));
}

extern __shared__ float smem_raw[];

__global__ __launch_bounds__(NTHREADS, 4)
void msse_kernel(const float* __restrict__ x,
                 const int* __restrict__ mask,
                 float* __restrict__ out)
{
    const int s0    = blockIdx.x * TSTART;    // global start of this L tile
    const int dbase = blockIdx.y * DT;        // float4-group base of D tile
    const int b     = blockIdx.z;
    const int tid   = threadIdx.x;

    float4* s4  = reinterpret_cast<float4*>(smem_raw);           // NS4*DT f4
    float*  inv = reinterpret_cast<float*>(s4 + NS4 * DT);       // 4*TSTART

    const float4* xrow = reinterpret_cast<const float4*>(x + (size_t)b * L_DIM * D_DIM);
    const int*    mrow = mask + (size_t)b * L_DIM;

    // ---- phase 1 (tid<128): window-length reciprocals straight from global
    //      mask (L1-resident row). Runs concurrently with phase 2a issue. ----
    if (tid < TSTART) {
        const int g0 = s0 + tid;
        int c = 0, c4 = 0, c8 = 0, c16 = 0;
        #pragma unroll
        for (int k = 0; k < 32; k++) {
            int g = g0 + k;
            c += (g < L_DIM) ? __ldg(mrow + g) : 0;
            if (k == 3)  c4  = c;
            if (k == 7)  c8  = c;
            if (k == 15) c16 = c;
        }
        int c32 = c;
        inv[0 * TSTART + tid] = 1.0f / (float)(c4  > 1 ? c4  : 1);
        inv[1 * TSTART + tid] = 1.0f / (float)(c8  > 1 ? c8  : 1);
        inv[2 * TSTART + tid] = 1.0f / (float)(c16 > 1 ? c16 : 1);
        inv[3 * TSTART + tid] = 1.0f / (float)(c32 > 1 ? c32 : 1);
    }

    // ---- phase 2a: build s4 directly from global. x loads are UNCONDITIONAL
    //      (clamped address) so they issue immediately with no mask dependency;
    //      masking applied as FFMA by a float mask loaded per-register. ----
    for (int i = tid; i < NS4 * DT; i += NTHREADS) {
        const int p = i >> 3;
        const int q = i & 7;
        const int g = s0 + p;

        float4 acc = make_float4(0.f, 0.f, 0.f, 0.f);
        #pragma unroll
        for (int k = 0; k < 4; k++) {
            int gg = g + k;
            int gc = gg < L_DIM ? gg : (L_DIM - 1);
            float m = (gg < L_DIM) ? (float)__ldg(mrow + gg) : 0.f;
            float4 v = __ldg(xrow + (size_t)gc * DVF + dbase + q);
            acc = fma4(m, v, acc);
        }
        s4[i] = acc;
    }

    __syncthreads();   // the only barrier: s4 + inv ready

    // ---- phase 3: pair-start sweep. Each thread produces ALL windows for
    //      starts j0 and j1=j0+4 from one pass over a0..a8 (9 LDS / 2 starts). ----
    {
        const int q   = tid & 7;
        const int idx = tid >> 3;        // 0..63
        const int jm  = idx & 3;
        const int k   = idx >> 2;        // 0..15
        const int j0  = jm + 8 * k;      // first start of pair
        const int j1  = j0 + 4;
        const int gi0 = s0 + j0;
        const int gi1 = s0 + j1;
        const int oq  = dbase + q;

        float4* outb = reinterpret_cast<float4*>(out + (size_t)b * ROWS * D_DIM);
        const float4* sp = s4 + j0 * DT + q;   // a_k = sp[k*4*DT]

        // a0
        float4 a    = sp[0];
        float4 accA = a;                                   // j0 running sum
        if (gi0 <= L_DIM - 4)
            outb[(OFF4 + gi0) * DVF + oq] = scl4(a, inv[0 * TSTART + j0]);
        // a1
        a = sp[4 * DT];
        float4 accB = a;                                   // j1 running sum
        if (gi1 <= L_DIM - 4)
            outb[(OFF4 + gi1) * DVF + oq] = scl4(a, inv[0 * TSTART + j1]);
        accA = add4(accA, a);
        if (gi0 <= L_DIM - 8)
            outb[(OFF8 + gi0) * DVF + oq] = scl4(accA, inv[1 * TSTART + j0]);
        // a2
        a = sp[8 * DT];
        accB = add4(accB, a);
        if (gi1 <= L_DIM - 8)
            outb[(OFF8 + gi1) * DVF + oq] = scl4(accB, inv[1 * TSTART + j1]);
        accA = add4(accA, a);
        // a3
        a = sp[12 * DT];
        accA = add4(accA, a);
        if (gi0 <= L_DIM - 16)
            outb[(OFF16 + gi0) * DVF + oq] = scl4(accA, inv[2 * TSTART + j0]);
        accB = add4(accB, a);
        // a4
        a = sp[16 * DT];
        accB = add4(accB, a);
        if (gi1 <= L_DIM - 16)
            outb[(OFF16 + gi1) * DVF + oq] = scl4(accB, inv[2 * TSTART + j1]);
        accA = add4(accA, a);
        // a5
        a = sp[20 * DT];
        accA = add4(accA, a);
        accB = add4(accB, a);
        // a6
        a = sp[24 * DT];
        accA = add4(accA, a);
        accB = add4(accB, a);
        // a7
        a = sp[28 * DT];
        accA = add4(accA, a);
        if (gi0 <= L_DIM - 32)
            outb[(OFF32 + gi0) * DVF + oq] = scl4(accA, inv[3 * TSTART + j0]);
        accB = add4(accB, a);
        // a8
        a = sp[32 * DT];
        accB = add4(accB, a);
        if (gi1 <= L_DIM - 32)
            outb[(OFF32 + gi1) * DVF + oq] = scl4(accB, inv[3 * TSTART + j1]);
    }
}

extern "C" void kernel_launch(void* const* d_in, const int* in_sizes, int n_in,
                              void* d_out, int out_size)
{
    const float* x    = (const float*)d_in[0];
    const int*   mask = (const int*)d_in[1];
    float*       out  = (float*)d_out;

    cudaFuncSetAttribute(msse_kernel,
                         cudaFuncAttributeMaxDynamicSharedMemorySize, SMEM_BYTES);

    dim3 grid(L_DIM / TSTART, NDT, B_DIM);   // 8 x 4 x 128 = 4096 CTAs
    msse_kernel<<<grid, NTHREADS, SMEM_BYTES>>>(x, mask, out);
}

// round 8
// speedup vs baseline: 1.5000x; 1.1571x over previous
#include <cuda_runtime.h>
#include <cuda_bf16.h>

// Problem constants
#define B_DIM 128
#define L_DIM 1024
#define D_DIM 128
#define DVF   32          // D/4 float4 groups (full row)
#define DT    8           // float4 groups per D-tile (D split 4 ways)
#define NDT   4
#define TSTART 128        // output start positions per L tile
#define NPOS  159         // TSTART + 31 halo positions (mask)
#define NS4   156         // sliding-4-sum rows needed: TSTART + 28
#define NTHREADS 512

// Output row offsets for window sizes 4, 8, 16, 32
#define OFF4  0
#define OFF8  1021
#define OFF16 2038
#define OFF32 3047
#define ROWS  4040

// Shared memory (floats): s4 + inv + msk(padded to 160)
#define SMEM_FLOATS (NS4 * DT * 4 + 4 * TSTART + 160)
#define SMEM_BYTES  (SMEM_FLOATS * 4)

__device__ __forceinline__ float4 add4(float4 a, float4 b) {
    return make_float4(a.x + b.x, a.y + b.y, a.z + b.z, a.w + b.w);
}
__device__ __forceinline__ float4 scl4(float4 a, float s) {
    return make_float4(a.x * s, a.y * s, a.z * s, a.w * s);
}

extern __shared__ float smem_raw[];

__global__ __launch_bounds__(NTHREADS, 4)
void msse_kernel(const float* __restrict__ x,
                 const int* __restrict__ mask,
                 float* __restrict__ out)
{
    const int s0    = blockIdx.x * TSTART;    // global start of this L tile
    const int dbase = blockIdx.y * DT;        // float4-group base of D tile
    const int b     = blockIdx.z;
    const int tid   = threadIdx.x;

    float4* s4  = reinterpret_cast<float4*>(smem_raw);           // NS4*DT f4
    float*  inv = reinterpret_cast<float*>(s4 + NS4 * DT);       // 4*TSTART
    int*    msk = reinterpret_cast<int*>(inv + 4 * TSTART);      // 160

    // ---- phase 1: load mask tile (with halo), zero-pad past L ----
    const int* mrow = mask + (size_t)b * L_DIM;
    for (int p = tid; p < NPOS; p += NTHREADS) {
        int g = s0 + p;
        msk[p] = (g < L_DIM) ? mrow[g] : 0;
    }
    __syncthreads();

    const float4* xrow = reinterpret_cast<const float4*>(x + (size_t)b * L_DIM * D_DIM);
    const float4 fz = make_float4(0.f, 0.f, 0.f, 0.f);

    // ---- phase 2a: build s4 directly from global (4 masked/predicated loads
    //      each — predicated-off loads move no bytes; mask=0 half the time
    //      so x read traffic is ~halved). L2 absorbs the 4x row reuse. ----
    for (int i = tid; i < NS4 * DT; i += NTHREADS) {
        int p = i >> 3;
        int q = i & 7;
        const float4* base = xrow + (size_t)(s0 + p) * DVF + dbase + q;
        float4 acc = fz;
        #pragma unroll
        for (int k = 0; k < 4; k++) {
            if (msk[p + k]) acc = add4(acc, __ldg(base + k * DVF));
        }
        s4[i] = acc;
    }

    // ---- phase 2b: per-start window-length reciprocals ----
    if (tid < TSTART) {
        int j = tid;
        int c = 0;
        #pragma unroll
        for (int k = 0; k < 4; k++)  c += msk[j + k];
        int c4 = c;
        #pragma unroll
        for (int k = 4; k < 8; k++)  c += msk[j + k];
        int c8 = c;
        #pragma unroll
        for (int k = 8; k < 16; k++) c += msk[j + k];
        int c16 = c;
        #pragma unroll
        for (int k = 16; k < 32; k++) c += msk[j + k];
        int c32 = c;
        inv[0 * TSTART + j] = 1.0f / (float)(c4  > 1 ? c4  : 1);
        inv[1 * TSTART + j] = 1.0f / (float)(c8  > 1 ? c8  : 1);
        inv[2 * TSTART + j] = 1.0f / (float)(c16 > 1 ? c16 : 1);
        inv[3 * TSTART + j] = 1.0f / (float)(c32 > 1 ? c32 : 1);
    }
    __syncthreads();

    // ---- phase 3: pair-start sweep (9 LDS.128 per 2 starts), all output
    //      stores streaming (.cs) — output is write-once, keep x in L2. ----
    {
        const int q   = tid & 7;
        const int idx = tid >> 3;        // 0..63
        const int jm  = idx & 3;
        const int k   = idx >> 2;        // 0..15
        const int j0  = jm + 8 * k;      // first start of pair
        const int j1  = j0 + 4;
        const int gi0 = s0 + j0;
        const int gi1 = s0 + j1;
        const int oq  = dbase + q;

        float4* outb = reinterpret_cast<float4*>(out + (size_t)b * ROWS * D_DIM);
        const float4* sp = s4 + j0 * DT + q;   // a_k = sp[k*4*DT]

        // a0
        float4 a    = sp[0];
        float4 accA = a;                                   // j0 running sum
        if (gi0 <= L_DIM - 4)
            __stcs(&outb[(OFF4 + gi0) * DVF + oq], scl4(a, inv[0 * TSTART + j0]));
        // a1
        a = sp[4 * DT];
        float4 accB = a;                                   // j1 running sum
        if (gi1 <= L_DIM - 4)
            __stcs(&outb[(OFF4 + gi1) * DVF + oq], scl4(a, inv[0 * TSTART + j1]));
        accA = add4(accA, a);
        if (gi0 <= L_DIM - 8)
            __stcs(&outb[(OFF8 + gi0) * DVF + oq], scl4(accA, inv[1 * TSTART + j0]));
        // a2
        a = sp[8 * DT];
        accB = add4(accB, a);
        if (gi1 <= L_DIM - 8)
            __stcs(&outb[(OFF8 + gi1) * DVF + oq], scl4(accB, inv[1 * TSTART + j1]));
        accA = add4(accA, a);
        // a3
        a = sp[12 * DT];
        accA = add4(accA, a);
        if (gi0 <= L_DIM - 16)
            __stcs(&outb[(OFF16 + gi0) * DVF + oq], scl4(accA, inv[2 * TSTART + j0]));
        accB = add4(accB, a);
        // a4
        a = sp[16 * DT];
        accB = add4(accB, a);
        if (gi1 <= L_DIM - 16)
            __stcs(&outb[(OFF16 + gi1) * DVF + oq], scl4(accB, inv[2 * TSTART + j1]));
        accA = add4(accA, a);
        // a5
        a = sp[20 * DT];
        accA = add4(accA, a);
        accB = add4(accB, a);
        // a6
        a = sp[24 * DT];
        accA = add4(accA, a);
        accB = add4(accB, a);
        // a7
        a = sp[28 * DT];
        accA = add4(accA, a);
        if (gi0 <= L_DIM - 32)
            __stcs(&outb[(OFF32 + gi0) * DVF + oq], scl4(accA, inv[3 * TSTART + j0]));
        accB = add4(accB, a);
        // a8
        a = sp[32 * DT];
        accB = add4(accB, a);
        if (gi1 <= L_DIM - 32)
            __stcs(&outb[(OFF32 + gi1) * DVF + oq], scl4(accB, inv[3 * TSTART + j1]));
    }
}

extern "C" void kernel_launch(void* const* d_in, const int* in_sizes, int n_in,
                              void* d_out, int out_size)
{
    const float* x    = (const float*)d_in[0];
    const int*   mask = (const int*)d_in[1];
    float*       out  = (float*)d_out;

    cudaFuncSetAttribute(msse_kernel,
                         cudaFuncAttributeMaxDynamicSharedMemorySize, SMEM_BYTES);

    dim3 grid(L_DIM / TSTART, NDT, B_DIM);   // 8 x 4 x 128 = 4096 CTAs
    msse_kernel<<<grid, NTHREADS, SMEM_BYTES>>>(x, mask, out);
}

// round 9
// speedup vs baseline: 1.5126x; 1.0084x over previous
#include <cuda_runtime.h>
#include <cuda_bf16.h>

// Problem constants
#define B_DIM 128
#define L_DIM 1024
#define D_DIM 128
#define DVF   32          // D/4 float4 groups (full row)
#define DT    8           // float4 groups per D-tile (D split 4 ways)
#define NDT   4
#define TSTART 128        // output start positions per L tile
#define NPOS  159         // TSTART + 31 halo positions (mask)
#define NS4   156         // sliding-4-sum rows needed: TSTART + 28
#define NTHREADS 256

// Output row offsets for window sizes 4, 8, 16, 32
#define OFF4  0
#define OFF8  1021
#define OFF16 2038
#define OFF32 3047
#define ROWS  4040

// Shared memory (floats): s4 + inv + msk(padded to 160)
#define SMEM_FLOATS (NS4 * DT * 4 + 4 * TSTART + 160)
#define SMEM_BYTES  (SMEM_FLOATS * 4)

__device__ __forceinline__ float4 add4(float4 a, float4 b) {
    return make_float4(a.x + b.x, a.y + b.y, a.z + b.z, a.w + b.w);
}
__device__ __forceinline__ float4 scl4(float4 a, float s) {
    return make_float4(a.x * s, a.y * s, a.z * s, a.w * s);
}

extern __shared__ float smem_raw[];

__global__ __launch_bounds__(NTHREADS, 8)
void msse_kernel(const float* __restrict__ x,
                 const int* __restrict__ mask,
                 float* __restrict__ out)
{
    const int s0    = blockIdx.x * TSTART;    // global start of this L tile
    const int dbase = blockIdx.y * DT;        // float4-group base of D tile
    const int b     = blockIdx.z;
    const int tid   = threadIdx.x;

    float4* s4  = reinterpret_cast<float4*>(smem_raw);           // NS4*DT f4
    float*  inv = reinterpret_cast<float*>(s4 + NS4 * DT);       // 4*TSTART
    int*    msk = reinterpret_cast<int*>(inv + 4 * TSTART);      // 160

    // ---- phase 1: load mask tile (with halo), zero-pad past L ----
    const int* mrow = mask + (size_t)b * L_DIM;
    for (int p = tid; p < NPOS; p += NTHREADS) {
        int g = s0 + p;
        msk[p] = (g < L_DIM) ? mrow[g] : 0;
    }
    __syncthreads();

    const float4* xrow = reinterpret_cast<const float4*>(x + (size_t)b * L_DIM * D_DIM);
    const float4 fz = make_float4(0.f, 0.f, 0.f, 0.f);

    // ---- phase 2a: build s4 directly from global (4 masked/predicated loads
    //      each — predicated-off loads move no bytes). L2 absorbs 4x reuse. ----
    for (int i = tid; i < NS4 * DT; i += NTHREADS) {
        int p = i >> 3;
        int q = i & 7;
        const float4* base = xrow + (size_t)(s0 + p) * DVF + dbase + q;
        float4 acc = fz;
        #pragma unroll
        for (int k = 0; k < 4; k++) {
            if (msk[p + k]) acc = add4(acc, __ldg(base + k * DVF));
        }
        s4[i] = acc;
    }

    // ---- phase 2b: per-start window-length reciprocals ----
    if (tid < TSTART) {
        int j = tid;
        int c = 0;
        #pragma unroll
        for (int k = 0; k < 4; k++)  c += msk[j + k];
        int c4 = c;
        #pragma unroll
        for (int k = 4; k < 8; k++)  c += msk[j + k];
        int c8 = c;
        #pragma unroll
        for (int k = 8; k < 16; k++) c += msk[j + k];
        int c16 = c;
        #pragma unroll
        for (int k = 16; k < 32; k++) c += msk[j + k];
        int c32 = c;
        inv[0 * TSTART + j] = 1.0f / (float)(c4  > 1 ? c4  : 1);
        inv[1 * TSTART + j] = 1.0f / (float)(c8  > 1 ? c8  : 1);
        inv[2 * TSTART + j] = 1.0f / (float)(c16 > 1 ? c16 : 1);
        inv[3 * TSTART + j] = 1.0f / (float)(c32 > 1 ? c32 : 1);
    }
    __syncthreads();

    // ---- phase 3: pair-start sweep (9 LDS.128 per 2 starts), streaming
    //      stores. 256 threads -> each thread handles 2 pairs (4 starts). ----
    #pragma unroll
    for (int half = 0; half < 2; half++) {
        const int t   = tid + half * NTHREADS;  // virtual tid 0..511
        const int q   = t & 7;
        const int idx = t >> 3;          // 0..63
        const int jm  = idx & 3;
        const int k   = idx >> 2;        // 0..15
        const int j0  = jm + 8 * k;      // first start of pair
        const int j1  = j0 + 4;
        const int gi0 = s0 + j0;
        const int gi1 = s0 + j1;
        const int oq  = dbase + q;

        float4* outb = reinterpret_cast<float4*>(out + (size_t)b * ROWS * D_DIM);
        const float4* sp = s4 + j0 * DT + q;   // a_k = sp[k*4*DT]

        // a0
        float4 a    = sp[0];
        float4 accA = a;                                   // j0 running sum
        if (gi0 <= L_DIM - 4)
            __stcs(&outb[(OFF4 + gi0) * DVF + oq], scl4(a, inv[0 * TSTART + j0]));
        // a1
        a = sp[4 * DT];
        float4 accB = a;                                   // j1 running sum
        if (gi1 <= L_DIM - 4)
            __stcs(&outb[(OFF4 + gi1) * DVF + oq], scl4(a, inv[0 * TSTART + j1]));
        accA = add4(accA, a);
        if (gi0 <= L_DIM - 8)
            __stcs(&outb[(OFF8 + gi0) * DVF + oq], scl4(accA, inv[1 * TSTART + j0]));
        // a2
        a = sp[8 * DT];
        accB = add4(accB, a);
        if (gi1 <= L_DIM - 8)
            __stcs(&outb[(OFF8 + gi1) * DVF + oq], scl4(accB, inv[1 * TSTART + j1]));
        accA = add4(accA, a);
        // a3
        a = sp[12 * DT];
        accA = add4(accA, a);
        if (gi0 <= L_DIM - 16)
            __stcs(&outb[(OFF16 + gi0) * DVF + oq], scl4(accA, inv[2 * TSTART + j0]));
        accB = add4(accB, a);
        // a4
        a = sp[16 * DT];
        accB = add4(accB, a);
        if (gi1 <= L_DIM - 16)
            __stcs(&outb[(OFF16 + gi1) * DVF + oq], scl4(accB, inv[2 * TSTART + j1]));
        accA = add4(accA, a);
        // a5
        a = sp[20 * DT];
        accA = add4(accA, a);
        accB = add4(accB, a);
        // a6
        a = sp[24 * DT];
        accA = add4(accA, a);
        accB = add4(accB, a);
        // a7
        a = sp[28 * DT];
        accA = add4(accA, a);
        if (gi0 <= L_DIM - 32)
            __stcs(&outb[(OFF32 + gi0) * DVF + oq], scl4(accA, inv[3 * TSTART + j0]));
        accB = add4(accB, a);
        // a8
        a = sp[32 * DT];
        accB = add4(accB, a);
        if (gi1 <= L_DIM - 32)
            __stcs(&outb[(OFF32 + gi1) * DVF + oq], scl4(accB, inv[3 * TSTART + j1]));
    }
}

extern "C" void kernel_launch(void* const* d_in, const int* in_sizes, int n_in,
                              void* d_out, int out_size)
{
    const float* x    = (const float*)d_in[0];
    const int*   mask = (const int*)d_in[1];
    float*       out  = (float*)d_out;

    cudaFuncSetAttribute(msse_kernel,
                         cudaFuncAttributeMaxDynamicSharedMemorySize, SMEM_BYTES);

    dim3 grid(L_DIM / TSTART, NDT, B_DIM);   // 8 x 4 x 128 = 4096 CTAs
    msse_kernel<<<grid, NTHREADS, SMEM_BYTES>>>(x, mask, out);
}